// round 3
// baseline (speedup 1.0000x reference)
#include <cuda_runtime.h>
#include <cstddef>

// Problem constants (fixed by the dataset)
#define NN 50000
#define EE 800000
#define HH 64      // hidden
#define DC 128     // node in channels
#define EC 16      // edge in channels
#define LL 3
#define EPS_MSG 1e-7f
#define LN_EPS 1e-5f

// ---------------- device scratch (no cudaMalloc allowed) ----------------
__device__ float g_ea[(size_t)EE * HH];    // encoded edge features, 204.8 MB
__device__ float g_h[(size_t)NN * HH];     // node state
__device__ float g_z[(size_t)NN * HH];     // pre-normed layer input
__device__ float g_agg[(size_t)NN * HH];   // conv output (agg + root)
__device__ float g_t1[(size_t)NN * 2 * HH];// MLP hidden
__device__ int   g_deg[NN];
__device__ int   g_rowptr[NN + 1];
__device__ int   g_cursor[NN];
__device__ int   g_perm[EE];
__device__ int   g_psrc[EE];

// ---------------- packed f32x2 FMA helpers ----------------
__device__ __forceinline__ unsigned long long pk2(float x, float y) {
    unsigned long long r;
    asm("mov.b64 %0, {%1,%2};" : "=l"(r) : "f"(x), "f"(y));
    return r;
}
__device__ __forceinline__ float2 upk2(unsigned long long v) {
    float2 r;
    asm("mov.b64 {%0,%1}, %2;" : "=f"(r.x), "=f"(r.y) : "l"(v));
    return r;
}
// c += a * b (elementwise, a splatted)
__device__ __forceinline__ float2 ffma2(float a, float2 b, float2 c) {
    unsigned long long ra = pk2(a, a);
    unsigned long long rb = pk2(b.x, b.y);
    unsigned long long rc = pk2(c.x, c.y);
    asm("fma.rn.f32x2 %0, %1, %2, %0;" : "+l"(rc) : "l"(ra), "l"(rb));
    return upk2(rc);
}

// ---------------- CSR build: histogram / scan / scatter ----------------
__global__ void init_deg_kernel(int* __restrict__ deg) {
    int i = blockIdx.x * blockDim.x + threadIdx.x;
    if (i < NN) deg[i] = 0;
}

__global__ void hist_kernel(const int* __restrict__ dst, int* __restrict__ deg) {
    int e = blockIdx.x * blockDim.x + threadIdx.x;
    if (e < EE) atomicAdd(&deg[dst[e]], 1);
}

__global__ void scan_kernel(const int* __restrict__ deg, int* __restrict__ rowptr,
                            int* __restrict__ cursor) {
    __shared__ int sh[1024];
    const int tid = threadIdx.x;
    const int CH = (NN + 1023) / 1024;
    const int base = tid * CH;
    int s = 0;
    for (int i = 0; i < CH; i++) {
        int j = base + i;
        if (j < NN) s += deg[j];
    }
    sh[tid] = s;
    __syncthreads();
    for (int off = 1; off < 1024; off <<= 1) {
        int v = (tid >= off) ? sh[tid - off] : 0;
        __syncthreads();
        sh[tid] += v;
        __syncthreads();
    }
    int run = (tid > 0) ? sh[tid - 1] : 0;
    for (int i = 0; i < CH; i++) {
        int j = base + i;
        if (j < NN) {
            rowptr[j] = run;
            cursor[j] = run;
            run += deg[j];
        }
    }
    if (tid == 0) rowptr[NN] = sh[1023];
}

__global__ void scatter_kernel(const int* __restrict__ src, const int* __restrict__ dst,
                               int* __restrict__ cursor, int* __restrict__ perm,
                               int* __restrict__ psrc) {
    int e = blockIdx.x * blockDim.x + threadIdx.x;
    if (e < EE) {
        int idx = atomicAdd(&cursor[dst[e]], 1);
        perm[idx] = e;
        psrc[idx] = src[e];
    }
}

// ---------------- edge encoder: ea = edge_attr @ edge_W + edge_b ----------------
// one warp per edge (grid-stride): lane l owns features {2l, 2l+1}
__global__ __launch_bounds__(256) void edge_enc_kernel(const float* __restrict__ eattr,
                                                       const float* __restrict__ W,
                                                       const float* __restrict__ b,
                                                       float* __restrict__ ea) {
    __shared__ float sW[EC * HH];  // 1024 floats
    __shared__ float sB[HH];
    const int tid = threadIdx.x;
    for (int i = tid; i < EC * HH; i += 256) sW[i] = W[i];
    if (tid < HH) sB[tid] = b[tid];
    __syncthreads();

    const int lane = tid & 31;
    int gw = (blockIdx.x * blockDim.x + tid) >> 5;
    const int nw = (gridDim.x * blockDim.x) >> 5;
    const float2 bv = *reinterpret_cast<const float2*>(&sB[2 * lane]);

    for (int e = gw; e < EE; e += nw) {
        float inv = 0.f;
        if (lane < EC) inv = eattr[(size_t)e * EC + lane];
        float2 acc = bv;
#pragma unroll
        for (int k = 0; k < EC; k++) {
            float vk = __shfl_sync(0xffffffffu, inv, k);
            float2 wv = *reinterpret_cast<const float2*>(&sW[k * HH + 2 * lane]);
            acc = ffma2(vk, wv, acc);
        }
        *reinterpret_cast<float2*>(&ea[(size_t)e * HH + 2 * lane]) = acc;
    }
}

// ---------------- softmax aggregation (one pass, no segment-max) --------------
// one warp per destination node; lane l owns features {2l, 2l+1}
__global__ __launch_bounds__(256) void agg_kernel(const float* __restrict__ z,
                                                  const float* __restrict__ ea,
                                                  const int* __restrict__ perm,
                                                  const int* __restrict__ psrc,
                                                  const int* __restrict__ rowptr,
                                                  const float* __restrict__ t_ptr,
                                                  float* __restrict__ out) {
    const int w = (blockIdx.x * blockDim.x + threadIdx.x) >> 5;
    if (w >= NN) return;
    const int lane = threadIdx.x & 31;
    const float t = t_ptr[0];

    const int beg = rowptr[w], end = rowptr[w + 1];
    float2 accP = make_float2(0.f, 0.f);
    float2 accM = make_float2(0.f, 0.f);
    for (int j = beg; j < end; j++) {
        const int e = perm[j];   // broadcast
        const int s = psrc[j];   // broadcast
        float2 zv = *reinterpret_cast<const float2*>(&z[(size_t)s * HH + 2 * lane]);
        float2 ev = *reinterpret_cast<const float2*>(&ea[(size_t)e * HH + 2 * lane]);
        float m0 = fmaxf(zv.x + ev.x, 0.f) + EPS_MSG;
        float m1 = fmaxf(zv.y + ev.y, 0.f) + EPS_MSG;
        // softmax weights without max-shift: exp values bounded (msg small, t=O(1))
        float p0 = __expf(m0 * t);
        float p1 = __expf(m1 * t);
        accP.x += p0; accP.y += p1;
        accM.x += m0 * p0; accM.y += m1 * p1;
    }
    float2 zd = *reinterpret_cast<const float2*>(&z[(size_t)w * HH + 2 * lane]);
    float2 o;
    o.x = (end > beg ? accM.x / accP.x : 0.f) + zd.x;
    o.y = (end > beg ? accM.y / accP.y : 0.f) + zd.y;
    *reinterpret_cast<float2*>(&out[(size_t)w * HH + 2 * lane]) = o;
}

// ---------------- LayerNorm + ReLU (64-wide rows), one warp per node ----------
__global__ __launch_bounds__(256) void ln_relu_kernel(const float* __restrict__ in,
                                                      const float* __restrict__ g,
                                                      const float* __restrict__ b,
                                                      float* __restrict__ out) {
    const int w = (blockIdx.x * blockDim.x + threadIdx.x) >> 5;
    if (w >= NN) return;
    const int lane = threadIdx.x & 31;
    float2 v = *reinterpret_cast<const float2*>(&in[(size_t)w * HH + 2 * lane]);
    float s1 = v.x + v.y;
    float s2 = v.x * v.x + v.y * v.y;
#pragma unroll
    for (int o = 16; o; o >>= 1) {
        s1 += __shfl_xor_sync(0xffffffffu, s1, o);
        s2 += __shfl_xor_sync(0xffffffffu, s2, o);
    }
    float mean = s1 * (1.f / HH);
    float var = s2 * (1.f / HH) - mean * mean;
    float rstd = rsqrtf(var + LN_EPS);
    float2 gg = *reinterpret_cast<const float2*>(&g[2 * lane]);
    float2 bb = *reinterpret_cast<const float2*>(&b[2 * lane]);
    float2 o2;
    o2.x = fmaxf((v.x - mean) * rstd * gg.x + bb.x, 0.f);
    o2.y = fmaxf((v.y - mean) * rstd * gg.y + bb.y, 0.f);
    *reinterpret_cast<float2*>(&out[(size_t)w * HH + 2 * lane]) = o2;
}

// ---------------- tiled GEMM with f32x2 FMA -----------------------------------
// C[M,NOUT] = A[M,K] @ W[K,NOUT] + bias, optional fused LN(128)+ReLU, optional residual.
// Block: 256 threads, MTILE=64 rows. Warp w owns rows w*8..w*8+7.
// NOUT=128: lane owns feats 4l..4l+3. NOUT=64: lane owns feats 2l..2l+1.
template <int K, int NOUT, bool LN_RELU>
__global__ __launch_bounds__(256) void gemm_kernel(const float* __restrict__ A,
                                                   const float* __restrict__ W,
                                                   const float* __restrict__ bias,
                                                   const float* __restrict__ lng,
                                                   const float* __restrict__ lnb,
                                                   const float* __restrict__ resid,
                                                   float* __restrict__ C, int M) {
    extern __shared__ float sh[];
    float* sA = sh;             // 64*K
    float* sW = sh + 64 * K;    // K*NOUT
    const int tid = threadIdx.x;
    const int m0 = blockIdx.x * 64;

    for (int idx = tid * 4; idx < 64 * K; idx += 256 * 4) {
        int row = idx / K, col = idx % K;
        float4 v = make_float4(0.f, 0.f, 0.f, 0.f);
        if (m0 + row < M)
            v = *reinterpret_cast<const float4*>(&A[(size_t)(m0 + row) * K + col]);
        *reinterpret_cast<float4*>(&sA[idx]) = v;
    }
    for (int idx = tid * 4; idx < K * NOUT; idx += 256 * 4)
        *reinterpret_cast<float4*>(&sW[idx]) = *reinterpret_cast<const float4*>(&W[idx]);
    __syncthreads();

    const int warp = tid >> 5, lane = tid & 31;
    const int r0 = warp * 8;

    if (NOUT == 128) {
        float2 acc[8][2];
#pragma unroll
        for (int r = 0; r < 8; r++) { acc[r][0] = make_float2(0.f, 0.f); acc[r][1] = make_float2(0.f, 0.f); }
#pragma unroll 4
        for (int k = 0; k < K; k++) {
            float2 w01 = *reinterpret_cast<const float2*>(&sW[k * 128 + 4 * lane]);
            float2 w23 = *reinterpret_cast<const float2*>(&sW[k * 128 + 4 * lane + 2]);
#pragma unroll
            for (int r = 0; r < 8; r++) {
                float a = sA[(r0 + r) * K + k];
                acc[r][0] = ffma2(a, w01, acc[r][0]);
                acc[r][1] = ffma2(a, w23, acc[r][1]);
            }
        }
        float4 bv = *reinterpret_cast<const float4*>(&bias[4 * lane]);
        float4 gv = *reinterpret_cast<const float4*>(&lng[4 * lane]);
        float4 tv = *reinterpret_cast<const float4*>(&lnb[4 * lane]);
#pragma unroll
        for (int r = 0; r < 8; r++) {
            int row = m0 + r0 + r;
            if (row >= M) break;  // warp-uniform
            float v0 = acc[r][0].x + bv.x, v1 = acc[r][0].y + bv.y;
            float v2 = acc[r][1].x + bv.z, v3 = acc[r][1].y + bv.w;
            float s1 = v0 + v1 + v2 + v3;
            float s2 = v0 * v0 + v1 * v1 + v2 * v2 + v3 * v3;
#pragma unroll
            for (int o = 16; o; o >>= 1) {
                s1 += __shfl_xor_sync(0xffffffffu, s1, o);
                s2 += __shfl_xor_sync(0xffffffffu, s2, o);
            }
            float mean = s1 * (1.f / 128.f);
            float var = s2 * (1.f / 128.f) - mean * mean;
            float rstd = rsqrtf(var + LN_EPS);
            v0 = fmaxf((v0 - mean) * rstd * gv.x + tv.x, 0.f);
            v1 = fmaxf((v1 - mean) * rstd * gv.y + tv.y, 0.f);
            v2 = fmaxf((v2 - mean) * rstd * gv.z + tv.z, 0.f);
            v3 = fmaxf((v3 - mean) * rstd * gv.w + tv.w, 0.f);
            *reinterpret_cast<float4*>(&C[(size_t)row * 128 + 4 * lane]) =
                make_float4(v0, v1, v2, v3);
        }
    } else {  // NOUT == 64
        float2 acc[8];
#pragma unroll
        for (int r = 0; r < 8; r++) acc[r] = make_float2(0.f, 0.f);
#pragma unroll 4
        for (int k = 0; k < K; k++) {
            float2 wv = *reinterpret_cast<const float2*>(&sW[k * 64 + 2 * lane]);
#pragma unroll
            for (int r = 0; r < 8; r++) {
                float a = sA[(r0 + r) * K + k];
                acc[r] = ffma2(a, wv, acc[r]);
            }
        }
        float2 bv = *reinterpret_cast<const float2*>(&bias[2 * lane]);
#pragma unroll
        for (int r = 0; r < 8; r++) {
            int row = m0 + r0 + r;
            if (row >= M) break;
            float2 o = make_float2(acc[r].x + bv.x, acc[r].y + bv.y);
            if (resid != nullptr) {
                float2 rv = *reinterpret_cast<const float2*>(&resid[(size_t)row * 64 + 2 * lane]);
                o.x += rv.x; o.y += rv.y;
            }
            *reinterpret_cast<float2*>(&C[(size_t)row * 64 + 2 * lane]) = o;
        }
    }
}

// ---------------- launch ------------------------------------------------------
extern "C" void kernel_launch(void* const* d_in, const int* in_sizes, int n_in,
                              void* d_out, int out_size) {
    const float* x      = (const float*)d_in[0];
    const int*   ei     = (const int*)d_in[1];
    const float* eattr  = (const float*)d_in[2];
    const float* node_W = (const float*)d_in[3];
    const float* node_b = (const float*)d_in[4];
    const float* edge_W = (const float*)d_in[5];
    const float* edge_b = (const float*)d_in[6];
    const float* t      = (const float*)d_in[7];
    const float* mlp1_W = (const float*)d_in[8];
    const float* mlp1_b = (const float*)d_in[9];
    const float* ln_g   = (const float*)d_in[10];
    const float* ln_b   = (const float*)d_in[11];
    const float* mlp2_W = (const float*)d_in[12];
    const float* mlp2_b = (const float*)d_in[13];
    const float* blk_g  = (const float*)d_in[14];
    const float* blk_b  = (const float*)d_in[15];
    float* out = (float*)d_out;

    const int* src = ei;
    const int* dst = ei + EE;

    float *p_ea, *p_h, *p_z, *p_agg, *p_t1;
    int *p_deg, *p_rowptr, *p_cursor, *p_perm, *p_psrc;
    cudaGetSymbolAddress((void**)&p_ea, g_ea);
    cudaGetSymbolAddress((void**)&p_h, g_h);
    cudaGetSymbolAddress((void**)&p_z, g_z);
    cudaGetSymbolAddress((void**)&p_agg, g_agg);
    cudaGetSymbolAddress((void**)&p_t1, g_t1);
    cudaGetSymbolAddress((void**)&p_deg, g_deg);
    cudaGetSymbolAddress((void**)&p_rowptr, g_rowptr);
    cudaGetSymbolAddress((void**)&p_cursor, g_cursor);
    cudaGetSymbolAddress((void**)&p_perm, g_perm);
    cudaGetSymbolAddress((void**)&p_psrc, g_psrc);

    cudaFuncSetAttribute(gemm_kernel<64, 128, true>,
                         cudaFuncAttributeMaxDynamicSharedMemorySize, 49152);
    cudaFuncSetAttribute(gemm_kernel<128, 64, false>,
                         cudaFuncAttributeMaxDynamicSharedMemorySize, 65536);

    const int warpBlocks = (NN * 32 + 255) / 256;   // 6250 (one warp per node)
    const int gemmBlocks = (NN + 63) / 64;          // 782

    // --- CSR build (reused across all layers) ---
    init_deg_kernel<<<(NN + 255) / 256, 256>>>(p_deg);
    hist_kernel<<<(EE + 255) / 256, 256>>>(dst, p_deg);
    scan_kernel<<<1, 1024>>>(p_deg, p_rowptr, p_cursor);
    scatter_kernel<<<(EE + 255) / 256, 256>>>(src, dst, p_cursor, p_perm, p_psrc);

    // --- encoders ---
    edge_enc_kernel<<<2048, 256>>>(eattr, edge_W, edge_b, p_ea);
    gemm_kernel<128, 64, false><<<gemmBlocks, 256, 65536>>>(
        x, node_W, node_b, nullptr, nullptr, nullptr, p_h, NN);

    // --- layers ---
    for (int i = 0; i < LL; i++) {
        const float* z = p_h;
        if (i > 0) {
            ln_relu_kernel<<<warpBlocks, 256>>>(p_h, blk_g + i * HH, blk_b + i * HH, p_z);
            z = p_z;
        }
        agg_kernel<<<warpBlocks, 256>>>(z, p_ea, p_perm, p_psrc, p_rowptr, t + i, p_agg);
        gemm_kernel<64, 128, true><<<gemmBlocks, 256, 49152>>>(
            p_agg, mlp1_W + (size_t)i * 64 * 128, mlp1_b + i * 128,
            ln_g + i * 128, ln_b + i * 128, nullptr, p_t1, NN);
        gemm_kernel<128, 64, false><<<gemmBlocks, 256, 65536>>>(
            p_t1, mlp2_W + (size_t)i * 128 * 64, mlp2_b + i * 64,
            nullptr, nullptr, (i > 0 ? p_h : nullptr), p_h, NN);
    }

    // --- final norm (uses blk_ln[0]) ---
    ln_relu_kernel<<<warpBlocks, 256>>>(p_h, blk_g, blk_b, out);
}